// round 5
// baseline (speedup 1.0000x reference)
#include <cuda_runtime.h>
#include <math.h>

#define BSZ  16
#define N    512
#define TILE 64
#define HALO 11
#define RG   (TILE + 2*HALO)   /* 86 */
#define RP   (RG + 2)          /* 88 */
#define HID  32
#define NPTS (BSZ*N*N)
#define SMEM_BYTES ((2 + 3*RG*RP)*4)   /* 90824 B -> 2 CTAs/SM at 512 thr */

typedef unsigned long long ull;

__device__ float  g_x0[NPTS];
__device__ float  g_x1[NPTS];
__device__ double g_acc[2];

__global__ void zero_acc_kernel() {
    if (threadIdx.x < 2) g_acc[threadIdx.x] = 0.0;
}

__device__ __forceinline__ ull pk(float a, float b) {
    ull r; asm("mov.b64 %0,{%1,%2};" : "=l"(r) : "f"(a), "f"(b)); return r;
}
__device__ __forceinline__ void upk(ull v, float& a, float& b) {
    asm("mov.b64 {%0,%1},%2;" : "=f"(a), "=f"(b) : "l"(v));
}
__device__ __forceinline__ float lo32(ull v) { float a,b; upk(v,a,b); return a; }
__device__ __forceinline__ float hi32(ull v) { float a,b; upk(v,a,b); return b; }
__device__ __forceinline__ ull fma2(ull a, ull b, ull c) {
    ull d; asm("fma.rn.f32x2 %0,%1,%2,%3;" : "=l"(d) : "l"(a), "l"(b), "l"(c)); return d;
}
__device__ __forceinline__ ull mul2(ull a, ull b) {
    ull d; asm("mul.rn.f32x2 %0,%1,%2;" : "=l"(d) : "l"(a), "l"(b)); return d;
}
__device__ __forceinline__ ull add2(ull a, ull b) {
    ull d; asm("add.rn.f32x2 %0,%1,%2;" : "=l"(d) : "l"(a), "l"(b)); return d;
}
__device__ __forceinline__ float tanh_ap(float x) {
    float y; asm("tanh.approx.f32 %0,%1;" : "=f"(y) : "f"(x)); return y;
}
__device__ __forceinline__ float sqrt_ap(float x) {
    float y; asm("sqrt.approx.f32 %0,%1;" : "=f"(y) : "f"(x)); return y;
}

__global__ void __launch_bounds__(512, 2)
iter_kernel(int dir, int zero_in,
            const float* __restrict__ f,  const float* __restrict__ kA,
            const float* __restrict__ W1, const float* __restrict__ b1g,
            const float* __restrict__ W2, const float* __restrict__ b2g)
{
    const float* xin  = dir ? g_x1 : g_x0;
    float*       xout = dir ? g_x0 : g_x1;

    extern __shared__ float smraw[];
    float* xsA = smraw + 2;          // front pad: window may read [-1]
    float* xsB = xsA + RG*RP;
    float* fs  = xsB + RG*RP;

    __shared__ ull sWa[HID], sWb[HID], sBb[HID], sWo[HID];
    __shared__ float ssb2;

    const int b  = blockIdx.z;
    const int tx = threadIdx.x, ty = threadIdx.y;   // 32 x 16
    const int tid = ty*32 + tx;
    const int gx0v = blockIdx.x * TILE - HALO;
    const int gy0v = blockIdx.y * TILE - HALO;

    const float* kb = kA + b * 9;
    const float k00 = __ldg(kb+0), k01 = __ldg(kb+1), k02 = __ldg(kb+2);
    const float k10 = __ldg(kb+3), k11 = __ldg(kb+4), k12 = __ldg(kb+5);
    const float k20 = __ldg(kb+6), k21 = __ldg(kb+7), k22 = __ldg(kb+8);
    const float tau = 0.5f / k11;
    const float nk00=-k00, nk01=-k01, nk02=-k02;
    const float nk10=-k10, nk11=-k11, nk12=-k12;
    const float nk20=-k20, nk21=-k21, nk22=-k22;
    const ull P00 = pk(nk00,nk00), P01 = pk(nk01,nk01), P02 = pk(nk02,nk02);
    const ull P10 = pk(nk10,nk10), P11 = pk(nk11,nk11), P12 = pk(nk12,nk12);
    const ull P20 = pk(nk20,nk20), P21 = pk(nk21,nk21), P22 = pk(nk22,nk22);
    const ull TAUP = pk(tau, tau);

    if (tid < HID) {
        float wa = W1[2*tid], wb = W1[2*tid+1], bv = b1g[tid], wo = 0.5f*W2[tid];
        sWa[tid] = pk(wa,wa); sWb[tid] = pk(wb,wb);
        sBb[tid] = pk(bv,bv); sWo[tid] = pk(wo,wo);
    } else if (tid == HID) ssb2 = b2g[0];

    // ---- region load (zero-padded outside domain); zero pong buffer ----
    // zero_in: fold sweep 0 into the load: x = tau * f
    const float* fb = f   + b * N * N;
    const float* xb = xin + b * N * N;
    for (int idx = tid; idx < RG*RG; idx += 512) {
        int ly = idx / RG, lx = idx - ly * RG;
        int gy = gy0v + ly, gx = gx0v + lx;
        float xv = 0.f, fv = 0.f;
        if ((unsigned)gx < N && (unsigned)gy < N) {
            int gi = gy * N + gx;
            fv = fb[gi];
            xv = zero_in ? (tau * fv) : xb[gi];
        }
        xsA[ly*RP + lx] = xv;
        fs [ly*RP + lx] = fv;
    }
    for (int idx = tid; idx < RG*RP; idx += 512) xsB[idx] = 0.f;
    __syncthreads();

    // ---- 10 Jacobi sweeps (packed f32x2, tree accumulator) ----
    float* cur = xsA;
    float* nxt = xsB;
    const int s0 = zero_in ? 1 : 0;
    #pragma unroll 1
    for (int s = s0; s < 10; ++s) {
        const int lo = s + 1, hi = RG - 1 - s;
        const int xlo = max(lo, -gx0v), xhi = min(hi, N - gx0v);
        const int ylo = max(lo, -gy0v), yhi = min(hi, N - gy0v);
        const int px0 = xlo & ~1;
        const int np  = (xhi - px0 + 1) >> 1;
        const int chunk = (yhi - ylo + 15) >> 4;
        const int ys = ylo + ty * chunk;
        const int ye = min(yhi, ys + chunk);
        if (ys < ye) {
            for (int ip = tx; ip < np; ip += 32) {
                const int px = px0 + 2*ip;
                const float o0 = ((unsigned)(gx0v + px)     < (unsigned)N) ? 1.f : 0.f;
                const float o1 = ((unsigned)(gx0v + px + 1) < (unsigned)N) ? 1.f : 0.f;
                const ull MASKP = pk(o0, o1);
                const float* rp = &cur[(ys-1)*RP + px];
                ull Ct = *(const ull*)rp;
                ull Lt = pk(rp[-1], lo32(Ct)), Rt = pk(hi32(Ct), rp[2]);
                rp += RP;
                ull Cm = *(const ull*)rp;
                ull Lm = pk(rp[-1], lo32(Cm)), Rm = pk(hi32(Cm), rp[2]);
                rp += RP;
                const float* fp = &fs[ys*RP + px];
                float* wp = &nxt[ys*RP + px];
                #pragma unroll 2
                for (int y = ys; y < ye; ++y) {
                    ull Cb = *(const ull*)rp;
                    ull Lb = pk(rp[-1], lo32(Cb)), Rb = pk(hi32(Cb), rp[2]);
                    ull a1 = *(const ull*)fp;
                    a1 = fma2(P00, Lt, a1); a1 = fma2(P01, Ct, a1); a1 = fma2(P02, Rt, a1);
                    ull a2 = mul2(P10, Lm); a2 = fma2(P11, Cm, a2); a2 = fma2(P12, Rm, a2);
                    ull a3 = mul2(P20, Lb); a3 = fma2(P21, Cb, a3); a3 = fma2(P22, Rb, a3);
                    ull acc = add2(a1, add2(a2, a3));
                    *(ull*)wp = mul2(fma2(TAUP, acc, Cm), MASKP);
                    Lt = Lm; Ct = Cm; Rt = Rm;
                    Lm = Lb; Cm = Cb; Rm = Rb;
                    rp += RP; fp += RP; wp += RP;
                }
            }
        }
        __syncthreads();
        float* t = cur; cur = nxt; nxt = t;
    }
    // cur: x after 10 sweeps, valid on [10,76)

    // ---- residual + LFA + MLP epilogue ----
    const float w2pih = 6.28318530717958647692f / 513.0f;
    const float cA = k00 + k22, cB = k02 + k20, cC = k01 + k21, cD = k10 + k12;
    const float sA = k22 - k00, sB = k02 - k20, sC = k21 - k01, sD = k12 - k10;
    float* xo = xout + b * N * N;

    // closed form for the linear half of gelu: sum_j 0.5*W2_j*v_j
    float S1 = 0.f, S2 = 0.f, S3 = ssb2;
    #pragma unroll 8
    for (int j = 0; j < HID; ++j) {
        float wo = lo32(sWo[j]);
        S1 = fmaf(wo, lo32(sWa[j]), S1);
        S2 = fmaf(wo, lo32(sWb[j]), S2);
        S3 = fmaf(wo, lo32(sBb[j]), S3);
    }

    const int ys_e = HALO + ty * 4;
    float s2a[4], c2a[4];
    #pragma unroll
    for (int i = 0; i < 4; ++i)
        __sincosf(w2pih * (float)(gy0v + ys_e + i - 256), &s2a[i], &c2a[i]);

    const ull K1 = pk(0.03567740814f, 0.03567740814f);
    const ull K0 = pk(0.7978845608f,  0.7978845608f);
    const ull Z  = pk(0.f, 0.f);

    #pragma unroll 1
    for (int g = 0; g < 2; ++g) {
        const int cx = HALO + tx + g*32;
        const int gx = gx0v + cx;
        float s1, c1;
        __sincosf(w2pih * (float)(gx - 256), &s1, &c1);

        const float* rp0 = &cur[(ys_e-1)*RP + cx];
        float t0 = rp0[-1],   t1 = rp0[0],  t2 = rp0[1];
        float m0 = rp0[RP-1], m1 = rp0[RP], m2 = rp0[RP+1];
        float rl[4], ll[4], xold[4];
        #pragma unroll
        for (int i = 0; i < 4; ++i) {
            const float* nn = rp0 + (i+2)*RP;
            float n0 = nn[-1], n1 = nn[0], n2 = nn[1];
            float a1 = fs[(ys_e+i)*RP + cx];
            a1 = fmaf(nk00,t0,a1); a1 = fmaf(nk01,t1,a1); a1 = fmaf(nk02,t2,a1);
            float a2 = nk10*m0;    a2 = fmaf(nk11,m1,a2); a2 = fmaf(nk12,m2,a2);
            float a3 = nk20*n0;    a3 = fmaf(nk21,n1,a3); a3 = fmaf(nk22,n2,a3);
            rl[i] = a1 + a2 + a3;
            xold[i] = m1;
            float ssv = s1*s2a[i], cc = c1*c2a[i], sc = s1*c2a[i], cs = c1*s2a[i];
            float cpp = cc - ssv, spp = sc + cs;
            float cpm = cc + ssv, spm = sc - cs;
            float ReS = cA*cpp + cB*cpm + cC*c2a[i] + cD*c1 + k11;
            float ImS = sA*spp + sB*spm + sC*s2a[i] + sD*s1;
            float Re = fmaf(-tau, ReS, 1.f);
            float Im = -tau * ImS;
            float mg2 = fmaf(Re, Re, Im*Im);
            ll[i] = mg2 * mg2 * sqrt_ap(mg2);   // |1-tau*S|^5
            t0=m0; t1=m1; t2=m2;
            m0=n0; m1=n1; m2=n2;
        }
        ull Rr0 = pk(rl[0], rl[1]), Rr1 = pk(rl[2], rl[3]);
        ull LF0 = pk(ll[0], ll[1]), LF1 = pk(ll[2], ll[3]);
        ull acc20 = Z, acc21 = Z;
        #pragma unroll 4
        for (int j = 0; j < HID; ++j) {
            const ull wa = sWa[j], wb = sWb[j], bb = sBb[j], wo = sWo[j];
            {
                ull v  = fma2(wa, LF0, fma2(wb, Rr0, bb));
                ull v2 = mul2(v, v);
                ull q  = fma2(v2, K1, K0);
                ull t  = mul2(v, q);
                float tl, th; upk(t, tl, th);
                ull T  = pk(tanh_ap(tl), tanh_ap(th));
                acc20 = fma2(mul2(v, wo), T, acc20);
            }
            {
                ull v  = fma2(wa, LF1, fma2(wb, Rr1, bb));
                ull v2 = mul2(v, v);
                ull q  = fma2(v2, K1, K0);
                ull t  = mul2(v, q);
                float tl, th; upk(t, tl, th);
                ull T  = pk(tanh_ap(tl), tanh_ap(th));
                acc21 = fma2(mul2(v, wo), T, acc21);
            }
        }
        float e0,e1,e2,e3;
        upk(acc20, e0, e1); upk(acc21, e2, e3);
        float ev[4] = {e0, e1, e2, e3};
        #pragma unroll
        for (int i = 0; i < 4; ++i) {
            float u = fmaf(S1, ll[i], fmaf(S2, rl[i], S3));
            xo[(gy0v + ys_e + i)*N + gx] = xold[i] + ev[i] + u;
        }
    }
}

__global__ void __launch_bounds__(256)
reduce_kernel(const float* __restrict__ f, const float* __restrict__ kA)
{
    __shared__ float xt[(TILE+2)*(TILE+4)];   // 66 x 68 pitch
    __shared__ float redbuf[16];
    const int b   = blockIdx.z;
    const int tid = threadIdx.y*32 + threadIdx.x;
    const float* xb = g_x1 + b*N*N;           // final x lives in g_x1
    const float* fb = f    + b*N*N;
    const int gx0v = blockIdx.x*TILE - 1;
    const int gy0v = blockIdx.y*TILE - 1;

    for (int idx = tid; idx < 66*66; idx += 256) {
        int ly = idx / 66, lx = idx - ly*66;
        int gy = gy0v + ly, gx = gx0v + lx;
        xt[ly*68 + lx] = ((unsigned)gx < N && (unsigned)gy < N) ? xb[gy*N + gx] : 0.f;
    }
    const float* kb = kA + b * 9;
    const float k00 = __ldg(kb+0), k01 = __ldg(kb+1), k02 = __ldg(kb+2);
    const float k10 = __ldg(kb+3), k11 = __ldg(kb+4), k12 = __ldg(kb+5);
    const float k20 = __ldg(kb+6), k21 = __ldg(kb+7), k22 = __ldg(kb+8);
    __syncthreads();

    float sr = 0.f, sf = 0.f;
    for (int ry = threadIdx.y; ry < TILE; ry += 8) {
        for (int rx = threadIdx.x; rx < TILE; rx += 32) {
            int ly = ry + 1, lx = rx + 1;
            const float* c = &xt[ly*68 + lx];
            float ax = k00*c[-69] + k01*c[-68] + k02*c[-67]
                     + k10*c[-1]  + k11*c[0]   + k12*c[1]
                     + k20*c[67]  + k21*c[68]  + k22*c[69];
            float fv = fb[(gy0v+ly)*N + (gx0v+lx)];
            float r = fv - ax;
            sr = fmaf(r, r, sr);
            sf = fmaf(fv, fv, sf);
        }
    }
    #pragma unroll
    for (int o = 16; o; o >>= 1) {
        sr += __shfl_down_sync(0xffffffffu, sr, o);
        sf += __shfl_down_sync(0xffffffffu, sf, o);
    }
    if (threadIdx.x == 0) { redbuf[threadIdx.y] = sr; redbuf[8+threadIdx.y] = sf; }
    __syncthreads();
    if (tid == 0) {
        float a = 0.f, bb = 0.f;
        #pragma unroll
        for (int i = 0; i < 8; ++i) { a += redbuf[i]; bb += redbuf[8+i]; }
        atomicAdd(&g_acc[0], (double)a);
        atomicAdd(&g_acc[1], (double)bb);
    }
}

__global__ void finalize_kernel(float* out) {
    out[0] = (float)sqrt(g_acc[0] / g_acc[1]);
}

extern "C" void kernel_launch(void* const* d_in, const int* in_sizes, int n_in,
                              void* d_out, int out_size)
{
    // metadata order: f, kernelA, u(unused), W1, b1, W2, b2, epoch(=201 -> K=3)
    const float* f  = (const float*)d_in[0];
    const float* kA = (const float*)d_in[1];
    const float* W1 = (const float*)d_in[3];
    const float* b1 = (const float*)d_in[4];
    const float* W2 = (const float*)d_in[5];
    const float* b2 = (const float*)d_in[6];
    float* out = (float*)d_out;

    cudaFuncSetAttribute(iter_kernel, cudaFuncAttributeMaxDynamicSharedMemorySize, SMEM_BYTES);

    dim3 grid(N/TILE, N/TILE, BSZ);   // (8, 8, 16)
    dim3 blk(32, 16);                 // 512 threads
    dim3 blkR(32, 8);

    zero_acc_kernel<<<1, 32>>>();
    // K = 3 outer cycles; x ping-pongs g_x0 <-> g_x1 (starts at zero)
    iter_kernel<<<grid, blk, SMEM_BYTES>>>(0, 1, f, kA, W1, b1, W2, b2); // 0 -> x1
    iter_kernel<<<grid, blk, SMEM_BYTES>>>(1, 0, f, kA, W1, b1, W2, b2); // x1 -> x0
    iter_kernel<<<grid, blk, SMEM_BYTES>>>(0, 0, f, kA, W1, b1, W2, b2); // x0 -> x1
    reduce_kernel<<<grid, blkR>>>(f, kA);
    finalize_kernel<<<1, 1>>>(out);
}

// round 6
// speedup vs baseline: 1.2351x; 1.2351x over previous
#include <cuda_runtime.h>
#include <math.h>

#define BSZ  16
#define N    512
#define TILE 64
#define HALO 11
#define RG   (TILE + 2*HALO)   /* 86 */
#define RP   (RG + 2)          /* 88, multiple of 4 -> 16B rows */
#define HID  32
#define NPTS (BSZ*N*N)
#define SMEM_BYTES ((4 + 3*RG*RP)*4)   /* 4-float front pad (16B align) */

typedef unsigned long long ull;

__device__ float  g_x0[NPTS];
__device__ float  g_x1[NPTS];
__device__ double g_acc[2];

__global__ void zero_acc_kernel() {
    if (threadIdx.x < 2) g_acc[threadIdx.x] = 0.0;
}

__device__ __forceinline__ ull pk(float a, float b) {
    ull r; asm("mov.b64 %0,{%1,%2};" : "=l"(r) : "f"(a), "f"(b)); return r;
}
__device__ __forceinline__ void upk(ull v, float& a, float& b) {
    asm("mov.b64 {%0,%1},%2;" : "=f"(a), "=f"(b) : "l"(v));
}
__device__ __forceinline__ float lo32(ull v) { float a,b; upk(v,a,b); return a; }
__device__ __forceinline__ ull fma2(ull a, ull b, ull c) {
    ull d; asm("fma.rn.f32x2 %0,%1,%2,%3;" : "=l"(d) : "l"(a), "l"(b), "l"(c)); return d;
}
__device__ __forceinline__ ull mul2(ull a, ull b) {
    ull d; asm("mul.rn.f32x2 %0,%1,%2;" : "=l"(d) : "l"(a), "l"(b)); return d;
}
__device__ __forceinline__ ull add2(ull a, ull b) {
    ull d; asm("add.rn.f32x2 %0,%1,%2;" : "=l"(d) : "l"(a), "l"(b)); return d;
}
__device__ __forceinline__ float tanh_ap(float x) {
    float y; asm("tanh.approx.f32 %0,%1;" : "=f"(y) : "f"(x)); return y;
}
__device__ __forceinline__ float sqrt_ap(float x) {
    float y; asm("sqrt.approx.f32 %0,%1;" : "=f"(y) : "f"(x)); return y;
}

__global__ void __launch_bounds__(256, 2)
iter_kernel(int dir, int zero_in,
            const float* __restrict__ f,  const float* __restrict__ kA,
            const float* __restrict__ W1, const float* __restrict__ b1g,
            const float* __restrict__ W2, const float* __restrict__ b2g)
{
    const float* xin  = dir ? g_x1 : g_x0;
    float*       xout = dir ? g_x0 : g_x1;

    extern __shared__ float smraw[];
    float* xsA = smraw + 4;          // 16B-aligned; front pad for [-1] reads
    float* xsB = xsA + RG*RP;
    float* fs  = xsB + RG*RP;

    __shared__ ull sWa[HID], sWb[HID], sBb[HID], sWo[HID];
    __shared__ float ssb2;

    const int b  = blockIdx.z;
    const int tx = threadIdx.x, ty = threadIdx.y;   // 32 x 8
    const int tid = ty*32 + tx;
    const int gx0v = blockIdx.x * TILE - HALO;
    const int gy0v = blockIdx.y * TILE - HALO;

    const float* kb = kA + b * 9;
    const float k00 = __ldg(kb+0), k01 = __ldg(kb+1), k02 = __ldg(kb+2);
    const float k10 = __ldg(kb+3), k11 = __ldg(kb+4), k12 = __ldg(kb+5);
    const float k20 = __ldg(kb+6), k21 = __ldg(kb+7), k22 = __ldg(kb+8);
    const float tau = 0.5f / k11;
    const float nk00=-k00, nk01=-k01, nk02=-k02;
    const float nk10=-k10, nk11=-k11, nk12=-k12;
    const float nk20=-k20, nk21=-k21, nk22=-k22;
    const ull P00 = pk(nk00,nk00), P01 = pk(nk01,nk01), P02 = pk(nk02,nk02);
    const ull P10 = pk(nk10,nk10), P11 = pk(nk11,nk11), P12 = pk(nk12,nk12);
    const ull P20 = pk(nk20,nk20), P21 = pk(nk21,nk21), P22 = pk(nk22,nk22);
    const ull TAUP = pk(tau, tau);

    if (tid < HID) {
        float wa = W1[2*tid], wb = W1[2*tid+1], bv = b1g[tid], wo = 0.5f*W2[tid];
        sWa[tid] = pk(wa,wa); sWb[tid] = pk(wb,wb);
        sBb[tid] = pk(bv,bv); sWo[tid] = pk(wo,wo);
    } else if (tid == HID) ssb2 = b2g[0];

    // ---- region load (zero-padded outside domain); zero pong buffer ----
    const float* fb = f   + b * N * N;
    const float* xb = xin + b * N * N;
    for (int idx = tid; idx < RG*RG; idx += 256) {
        int ly = idx / RG, lx = idx - ly * RG;
        int gy = gy0v + ly, gx = gx0v + lx;
        float xv = 0.f, fv = 0.f;
        if ((unsigned)gx < N && (unsigned)gy < N) {
            int gi = gy * N + gx;
            fv = fb[gi];
            xv = zero_in ? (tau * fv) : xb[gi];
        }
        xsA[ly*RP + lx] = xv;
        fs [ly*RP + lx] = fv;
    }
    for (int idx = tid; idx < RG*RP; idx += 256) xsB[idx] = 0.f;
    __syncthreads();

    // ---- 10 Jacobi sweeps: 4-point quads (LDS.128), packed f32x2 ----
    float* cur = xsA;
    float* nxt = xsB;
    const int s0 = zero_in ? 1 : 0;
    #pragma unroll 1
    for (int s = s0; s < 10; ++s) {
        const int lo = s + 1, hi = RG - 1 - s;
        const int xlo = max(lo, -gx0v), xhi = min(hi, N - gx0v);
        const int ylo = max(lo, -gy0v), yhi = min(hi, N - gy0v);
        const int px0 = xlo & ~3;
        const int nq  = (xhi - px0 + 3) >> 2;
        const int chunk = (yhi - ylo + 7) >> 3;
        const int ys = ylo + ty * chunk;
        const int ye = min(yhi, ys + chunk);
        if (ys < ye && tx < nq) {
            const int px = px0 + 4*tx;
            const float o0 = ((unsigned)(gx0v + px)     < (unsigned)N) ? 1.f : 0.f;
            const float o1 = ((unsigned)(gx0v + px + 1) < (unsigned)N) ? 1.f : 0.f;
            const float o2 = ((unsigned)(gx0v + px + 2) < (unsigned)N) ? 1.f : 0.f;
            const float o3 = ((unsigned)(gx0v + px + 3) < (unsigned)N) ? 1.f : 0.f;
            const ull M01 = pk(o0, o1), M23 = pk(o2, o3);

            const float* rp = &cur[(ys-1)*RP + px];
            // rows held as: L pair(l,c0), A pair(c0,c1), D pair(c1,c2), B pair(c2,c3), R pair(c3,r)
            float4 vt = *(const float4*)rp;
            ull Lt = pk(rp[-1], vt.x), At = pk(vt.x, vt.y), Dt = pk(vt.y, vt.z),
                Bt = pk(vt.z, vt.w), Rt = pk(vt.w, rp[4]);
            rp += RP;
            float4 vm = *(const float4*)rp;
            ull Lm = pk(rp[-1], vm.x), Am = pk(vm.x, vm.y), Dm = pk(vm.y, vm.z),
                Bm = pk(vm.z, vm.w), Rm = pk(vm.w, rp[4]);
            rp += RP;
            const float* fp = &fs[ys*RP + px];
            float* wp = &nxt[ys*RP + px];
            #pragma unroll 2
            for (int y = ys; y < ye; ++y) {
                float4 vb = *(const float4*)rp;
                ull Lb = pk(rp[-1], vb.x), Ab = pk(vb.x, vb.y), Db = pk(vb.y, vb.z),
                    Bb = pk(vb.z, vb.w), Rb = pk(vb.w, rp[4]);
                float4 fv = *(const float4*)fp;
                // pair (p0,p1): L=Lx, C=Ax, R=Dx
                ull u1 = fma2(P01, At, pk(fv.x, fv.y));
                u1 = fma2(P00, Lt, u1); u1 = fma2(P02, Dt, u1);
                ull u2 = mul2(P10, Lm); u2 = fma2(P11, Am, u2); u2 = fma2(P12, Dm, u2);
                ull u3 = mul2(P20, Lb); u3 = fma2(P21, Ab, u3); u3 = fma2(P22, Db, u3);
                ull o01 = mul2(fma2(TAUP, add2(u1, add2(u2, u3)), Am), M01);
                // pair (p2,p3): L=Dx, C=Bx, R=Rx
                ull w1 = fma2(P01, Bt, pk(fv.z, fv.w));
                w1 = fma2(P00, Dt, w1); w1 = fma2(P02, Rt, w1);
                ull w2 = mul2(P10, Dm); w2 = fma2(P11, Bm, w2); w2 = fma2(P12, Rm, w2);
                ull w3 = mul2(P20, Db); w3 = fma2(P21, Bb, w3); w3 = fma2(P22, Rb, w3);
                ull o23 = mul2(fma2(TAUP, add2(w1, add2(w2, w3)), Bm), M23);
                float4 ov;
                upk(o01, ov.x, ov.y);
                upk(o23, ov.z, ov.w);
                *(float4*)wp = ov;
                Lt=Lm; At=Am; Dt=Dm; Bt=Bm; Rt=Rm;
                Lm=Lb; Am=Ab; Dm=Db; Bm=Bb; Rm=Rb;
                rp += RP; fp += RP; wp += RP;
            }
        }
        __syncthreads();
        float* t = cur; cur = nxt; nxt = t;
    }
    // cur: x after 10 sweeps, valid on [10,76)

    // ---- residual + LFA + MLP epilogue (R3 layout: 16x16 logical) ----
    const float w2pih = 6.28318530717958647692f / 513.0f;
    const float cA = k00 + k22, cB = k02 + k20, cC = k01 + k21, cD = k10 + k12;
    const float sA = k22 - k00, sB = k02 - k20, sC = k21 - k01, sD = k12 - k10;
    float* xo = xout + b * N * N;

    // closed form for the linear half of gelu: sum_j 0.5*W2_j*v_j
    float S1 = 0.f, S2 = 0.f, S3 = ssb2;
    #pragma unroll 8
    for (int j = 0; j < HID; ++j) {
        float wo = lo32(sWo[j]);
        S1 = fmaf(wo, lo32(sWa[j]), S1);
        S2 = fmaf(wo, lo32(sWb[j]), S2);
        S3 = fmaf(wo, lo32(sBb[j]), S3);
    }

    const int etx = tid & 15, ety = tid >> 4;   // 16 x 16 logical
    const int ys_e = HALO + ety * 4;
    float s2a[4], c2a[4];
    #pragma unroll
    for (int i = 0; i < 4; ++i)
        __sincosf(w2pih * (float)(gy0v + ys_e + i - 256), &s2a[i], &c2a[i]);

    const ull K1 = pk(0.03567740814f, 0.03567740814f);
    const ull K0 = pk(0.7978845608f,  0.7978845608f);
    const ull Z  = pk(0.f, 0.f);

    #pragma unroll 1
    for (int g = 0; g < 4; ++g) {
        const int cx = HALO + etx + g*16;
        const int gx = gx0v + cx;
        float s1, c1;
        __sincosf(w2pih * (float)(gx - 256), &s1, &c1);

        const float* rp0 = &cur[(ys_e-1)*RP + cx];
        float t0 = rp0[-1],   t1 = rp0[0],  t2 = rp0[1];
        float m0 = rp0[RP-1], m1 = rp0[RP], m2 = rp0[RP+1];
        float rl[4], ll[4], xold[4];
        #pragma unroll
        for (int i = 0; i < 4; ++i) {
            const float* nn = rp0 + (i+2)*RP;
            float n0 = nn[-1], n1 = nn[0], n2 = nn[1];
            float a1 = fs[(ys_e+i)*RP + cx];
            a1 = fmaf(nk00,t0,a1); a1 = fmaf(nk01,t1,a1); a1 = fmaf(nk02,t2,a1);
            float a2 = nk10*m0;    a2 = fmaf(nk11,m1,a2); a2 = fmaf(nk12,m2,a2);
            float a3 = nk20*n0;    a3 = fmaf(nk21,n1,a3); a3 = fmaf(nk22,n2,a3);
            rl[i] = a1 + a2 + a3;
            xold[i] = m1;
            float ssv = s1*s2a[i], cc = c1*c2a[i], sc = s1*c2a[i], cs = c1*s2a[i];
            float cpp = cc - ssv, spp = sc + cs;
            float cpm = cc + ssv, spm = sc - cs;
            float ReS = cA*cpp + cB*cpm + cC*c2a[i] + cD*c1 + k11;
            float ImS = sA*spp + sB*spm + sC*s2a[i] + sD*s1;
            float Re = fmaf(-tau, ReS, 1.f);
            float Im = -tau * ImS;
            float mg2 = fmaf(Re, Re, Im*Im);
            ll[i] = mg2 * mg2 * sqrt_ap(mg2);   // |1-tau*S|^5
            t0=m0; t1=m1; t2=m2;
            m0=n0; m1=n1; m2=n2;
        }
        ull Rr0 = pk(rl[0], rl[1]), Rr1 = pk(rl[2], rl[3]);
        ull LF0 = pk(ll[0], ll[1]), LF1 = pk(ll[2], ll[3]);
        ull acc20 = Z, acc21 = Z;
        #pragma unroll 4
        for (int j = 0; j < HID; ++j) {
            const ull wa = sWa[j], wb = sWb[j], bb = sBb[j], wo = sWo[j];
            {
                ull v  = fma2(wa, LF0, fma2(wb, Rr0, bb));
                ull v2 = mul2(v, v);
                ull q  = fma2(v2, K1, K0);
                ull t  = mul2(v, q);
                float tl, th; upk(t, tl, th);
                ull T  = pk(tanh_ap(tl), tanh_ap(th));
                acc20 = fma2(mul2(v, wo), T, acc20);
            }
            {
                ull v  = fma2(wa, LF1, fma2(wb, Rr1, bb));
                ull v2 = mul2(v, v);
                ull q  = fma2(v2, K1, K0);
                ull t  = mul2(v, q);
                float tl, th; upk(t, tl, th);
                ull T  = pk(tanh_ap(tl), tanh_ap(th));
                acc21 = fma2(mul2(v, wo), T, acc21);
            }
        }
        float e0,e1,e2,e3;
        upk(acc20, e0, e1); upk(acc21, e2, e3);
        float ev[4] = {e0, e1, e2, e3};
        #pragma unroll
        for (int i = 0; i < 4; ++i) {
            float u = fmaf(S1, ll[i], fmaf(S2, rl[i], S3));
            xo[(gy0v + ys_e + i)*N + gx] = xold[i] + ev[i] + u;
        }
    }
}

__global__ void __launch_bounds__(256)
reduce_kernel(const float* __restrict__ f, const float* __restrict__ kA)
{
    __shared__ float xt[(TILE+2)*(TILE+4)];   // 66 x 68 pitch
    __shared__ float redbuf[16];
    const int b   = blockIdx.z;
    const int tid = threadIdx.y*32 + threadIdx.x;
    const float* xb = g_x1 + b*N*N;           // final x lives in g_x1
    const float* fb = f    + b*N*N;
    const int gx0v = blockIdx.x*TILE - 1;
    const int gy0v = blockIdx.y*TILE - 1;

    for (int idx = tid; idx < 66*66; idx += 256) {
        int ly = idx / 66, lx = idx - ly*66;
        int gy = gy0v + ly, gx = gx0v + lx;
        xt[ly*68 + lx] = ((unsigned)gx < N && (unsigned)gy < N) ? xb[gy*N + gx] : 0.f;
    }
    const float* kb = kA + b * 9;
    const float k00 = __ldg(kb+0), k01 = __ldg(kb+1), k02 = __ldg(kb+2);
    const float k10 = __ldg(kb+3), k11 = __ldg(kb+4), k12 = __ldg(kb+5);
    const float k20 = __ldg(kb+6), k21 = __ldg(kb+7), k22 = __ldg(kb+8);
    __syncthreads();

    float sr = 0.f, sf = 0.f;
    for (int ry = threadIdx.y; ry < TILE; ry += 8) {
        for (int rx = threadIdx.x; rx < TILE; rx += 32) {
            int ly = ry + 1, lx = rx + 1;
            const float* c = &xt[ly*68 + lx];
            float ax = k00*c[-69] + k01*c[-68] + k02*c[-67]
                     + k10*c[-1]  + k11*c[0]   + k12*c[1]
                     + k20*c[67]  + k21*c[68]  + k22*c[69];
            float fv = fb[(gy0v+ly)*N + (gx0v+lx)];
            float r = fv - ax;
            sr = fmaf(r, r, sr);
            sf = fmaf(fv, fv, sf);
        }
    }
    #pragma unroll
    for (int o = 16; o; o >>= 1) {
        sr += __shfl_down_sync(0xffffffffu, sr, o);
        sf += __shfl_down_sync(0xffffffffu, sf, o);
    }
    if (threadIdx.x == 0) { redbuf[threadIdx.y] = sr; redbuf[8+threadIdx.y] = sf; }
    __syncthreads();
    if (tid == 0) {
        float a = 0.f, bb = 0.f;
        #pragma unroll
        for (int i = 0; i < 8; ++i) { a += redbuf[i]; bb += redbuf[8+i]; }
        atomicAdd(&g_acc[0], (double)a);
        atomicAdd(&g_acc[1], (double)bb);
    }
}

__global__ void finalize_kernel(float* out) {
    out[0] = (float)sqrt(g_acc[0] / g_acc[1]);
}

extern "C" void kernel_launch(void* const* d_in, const int* in_sizes, int n_in,
                              void* d_out, int out_size)
{
    // metadata order: f, kernelA, u(unused), W1, b1, W2, b2, epoch(=201 -> K=3)
    const float* f  = (const float*)d_in[0];
    const float* kA = (const float*)d_in[1];
    const float* W1 = (const float*)d_in[3];
    const float* b1 = (const float*)d_in[4];
    const float* W2 = (const float*)d_in[5];
    const float* b2 = (const float*)d_in[6];
    float* out = (float*)d_out;

    cudaFuncSetAttribute(iter_kernel, cudaFuncAttributeMaxDynamicSharedMemorySize, SMEM_BYTES);

    dim3 grid(N/TILE, N/TILE, BSZ);   // (8, 8, 16)
    dim3 blk(32, 8);                  // 256 threads
    dim3 blkR(32, 8);

    zero_acc_kernel<<<1, 32>>>();
    // K = 3 outer cycles; x ping-pongs g_x0 <-> g_x1 (starts at zero)
    iter_kernel<<<grid, blk, SMEM_BYTES>>>(0, 1, f, kA, W1, b1, W2, b2); // 0 -> x1
    iter_kernel<<<grid, blk, SMEM_BYTES>>>(1, 0, f, kA, W1, b1, W2, b2); // x1 -> x0
    iter_kernel<<<grid, blk, SMEM_BYTES>>>(0, 0, f, kA, W1, b1, W2, b2); // x0 -> x1
    reduce_kernel<<<grid, blkR>>>(f, kA);
    finalize_kernel<<<1, 1>>>(out);
}

// round 7
// speedup vs baseline: 1.3076x; 1.0587x over previous
#include <cuda_runtime.h>
#include <math.h>

#define BSZ  16
#define N    512
#define TILE 64
#define HALO 11
#define RG   (TILE + 2*HALO)   /* 86 */
#define RP   (RG + 2)          /* 88, multiple of 4 -> 16B rows */
#define HID  32
#define NPTS (BSZ*N*N)
#define SMEM_BYTES ((4 + 3*RG*RP)*4)   /* 4-float front pad (16B align) */

typedef unsigned long long ull;

__device__ float  g_x0[NPTS];
__device__ float  g_x1[NPTS];
__device__ double g_acc[2];

__global__ void zero_acc_kernel() {
    if (threadIdx.x < 2) g_acc[threadIdx.x] = 0.0;
}

__device__ __forceinline__ ull pk(float a, float b) {
    ull r; asm("mov.b64 %0,{%1,%2};" : "=l"(r) : "f"(a), "f"(b)); return r;
}
__device__ __forceinline__ void upk(ull v, float& a, float& b) {
    asm("mov.b64 {%0,%1},%2;" : "=f"(a), "=f"(b) : "l"(v));
}
__device__ __forceinline__ float lo32(ull v) { float a,b; upk(v,a,b); return a; }
__device__ __forceinline__ ull fma2(ull a, ull b, ull c) {
    ull d; asm("fma.rn.f32x2 %0,%1,%2,%3;" : "=l"(d) : "l"(a), "l"(b), "l"(c)); return d;
}
__device__ __forceinline__ ull mul2(ull a, ull b) {
    ull d; asm("mul.rn.f32x2 %0,%1,%2;" : "=l"(d) : "l"(a), "l"(b)); return d;
}
__device__ __forceinline__ ull add2(ull a, ull b) {
    ull d; asm("add.rn.f32x2 %0,%1,%2;" : "=l"(d) : "l"(a), "l"(b)); return d;
}
__device__ __forceinline__ float tanh_ap(float x) {
    float y; asm("tanh.approx.f32 %0,%1;" : "=f"(y) : "f"(x)); return y;
}
__device__ __forceinline__ float sqrt_ap(float x) {
    float y; asm("sqrt.approx.f32 %0,%1;" : "=f"(y) : "f"(x)); return y;
}

__global__ void __launch_bounds__(256, 2)
iter_kernel(int dir, int zero_in,
            const float* __restrict__ f,  const float* __restrict__ kA,
            const float* __restrict__ W1, const float* __restrict__ b1g,
            const float* __restrict__ W2, const float* __restrict__ b2g)
{
    const float* xin  = dir ? g_x1 : g_x0;
    float*       xout = dir ? g_x0 : g_x1;

    extern __shared__ float smraw[];
    float* xsA = smraw + 4;          // 16B-aligned; front pad for [-1] reads
    float* xsB = xsA + RG*RP;
    float* fs  = xsB + RG*RP;

    __shared__ ull sWa[HID], sWb[HID], sBb[HID], sWo[HID];
    __shared__ float ssb2;

    const int b  = blockIdx.z;
    const int tid = threadIdx.y*32 + threadIdx.x;   // 256 threads
    const int gx0v = blockIdx.x * TILE - HALO;
    const int gy0v = blockIdx.y * TILE - HALO;

    const float* kb = kA + b * 9;
    const float k00 = __ldg(kb+0), k01 = __ldg(kb+1), k02 = __ldg(kb+2);
    const float k10 = __ldg(kb+3), k11 = __ldg(kb+4), k12 = __ldg(kb+5);
    const float k20 = __ldg(kb+6), k21 = __ldg(kb+7), k22 = __ldg(kb+8);
    const float tau = 0.5f / k11;
    const float nk00=-k00, nk01=-k01, nk02=-k02;
    const float nk10=-k10, nk11=-k11, nk12=-k12;
    const float nk20=-k20, nk21=-k21, nk22=-k22;
    const ull P00 = pk(nk00,nk00), P01 = pk(nk01,nk01), P02 = pk(nk02,nk02);
    const ull P10 = pk(nk10,nk10), P11 = pk(nk11,nk11), P12 = pk(nk12,nk12);
    const ull P20 = pk(nk20,nk20), P21 = pk(nk21,nk21), P22 = pk(nk22,nk22);
    const ull TAUP = pk(tau, tau);

    if (tid < HID) {
        float wa = W1[2*tid], wb = W1[2*tid+1], bv = b1g[tid], wo = 0.5f*W2[tid];
        sWa[tid] = pk(wa,wa); sWb[tid] = pk(wb,wb);
        sBb[tid] = pk(bv,bv); sWo[tid] = pk(wo,wo);
    } else if (tid == HID) ssb2 = b2g[0];

    // ---- region load (zero-padded outside domain); zero pong buffer ----
    const float* fb = f   + b * N * N;
    const float* xb = xin + b * N * N;
    for (int idx = tid; idx < RG*RG; idx += 256) {
        int ly = idx / RG, lx = idx - ly * RG;
        int gy = gy0v + ly, gx = gx0v + lx;
        float xv = 0.f, fv = 0.f;
        if ((unsigned)gx < N && (unsigned)gy < N) {
            int gi = gy * N + gx;
            fv = fb[gi];
            xv = zero_in ? (tau * fv) : xb[gi];
        }
        xsA[ly*RP + lx] = xv;
        fs [ly*RP + lx] = fv;
    }
    for (int idx = tid; idx < RG*RP; idx += 256) xsB[idx] = 0.f;
    __syncthreads();

    // ---- 10 Jacobi sweeps: quad-major thread map (all lanes active) ----
    float* cur = xsA;
    float* nxt = xsB;
    const int s0 = zero_in ? 1 : 0;
    #pragma unroll 1
    for (int s = s0; s < 10; ++s) {
        const int lo = s + 1, hi = RG - 1 - s;
        const int xlo = max(lo, -gx0v), xhi = min(hi, N - gx0v);
        const int ylo = max(lo, -gy0v), yhi = min(hi, N - gy0v);
        const int px0 = xlo & ~3;
        const int nq  = (xhi - px0 + 3) >> 2;       // ~17..22 quads
        const int nstr = 256 / nq;                  // strips
        const int spanY = yhi - ylo;
        const int rpst = (spanY + nstr - 1) / nstr; // rows per strip
        const int qx = tid % nq;
        const int st = tid / nq;
        const int ys = ylo + st * rpst;
        const int ye = min(yhi, ys + rpst);
        if (st < nstr && ys < ye) {
            const int px = px0 + 4*qx;
            const float o0 = ((unsigned)(gx0v + px)     < (unsigned)N) ? 1.f : 0.f;
            const float o1 = ((unsigned)(gx0v + px + 1) < (unsigned)N) ? 1.f : 0.f;
            const float o2 = ((unsigned)(gx0v + px + 2) < (unsigned)N) ? 1.f : 0.f;
            const float o3 = ((unsigned)(gx0v + px + 3) < (unsigned)N) ? 1.f : 0.f;
            const ull M01 = pk(o0, o1), M23 = pk(o2, o3);

            const float* rp = &cur[(ys-1)*RP + px];
            // rows held as: L pair(l,c0), A pair(c0,c1), D pair(c1,c2), B pair(c2,c3), R pair(c3,r)
            float4 vt = *(const float4*)rp;
            ull Lt = pk(rp[-1], vt.x), At = pk(vt.x, vt.y), Dt = pk(vt.y, vt.z),
                Bt = pk(vt.z, vt.w), Rt = pk(vt.w, rp[4]);
            rp += RP;
            float4 vm = *(const float4*)rp;
            ull Lm = pk(rp[-1], vm.x), Am = pk(vm.x, vm.y), Dm = pk(vm.y, vm.z),
                Bm = pk(vm.z, vm.w), Rm = pk(vm.w, rp[4]);
            rp += RP;
            const float* fp = &fs[ys*RP + px];
            float* wp = &nxt[ys*RP + px];
            #pragma unroll 2
            for (int y = ys; y < ye; ++y) {
                float4 vb = *(const float4*)rp;
                ull Lb = pk(rp[-1], vb.x), Ab = pk(vb.x, vb.y), Db = pk(vb.y, vb.z),
                    Bb = pk(vb.z, vb.w), Rb = pk(vb.w, rp[4]);
                float4 fv = *(const float4*)fp;
                // pair (p0,p1): L=Lx, C=Ax, R=Dx
                ull u1 = fma2(P01, At, pk(fv.x, fv.y));
                u1 = fma2(P00, Lt, u1); u1 = fma2(P02, Dt, u1);
                ull u2 = mul2(P10, Lm); u2 = fma2(P11, Am, u2); u2 = fma2(P12, Dm, u2);
                ull u3 = mul2(P20, Lb); u3 = fma2(P21, Ab, u3); u3 = fma2(P22, Db, u3);
                ull o01 = mul2(fma2(TAUP, add2(u1, add2(u2, u3)), Am), M01);
                // pair (p2,p3): L=Dx, C=Bx, R=Rx
                ull w1 = fma2(P01, Bt, pk(fv.z, fv.w));
                w1 = fma2(P00, Dt, w1); w1 = fma2(P02, Rt, w1);
                ull w2 = mul2(P10, Dm); w2 = fma2(P11, Bm, w2); w2 = fma2(P12, Rm, w2);
                ull w3 = mul2(P20, Db); w3 = fma2(P21, Bb, w3); w3 = fma2(P22, Rb, w3);
                ull o23 = mul2(fma2(TAUP, add2(w1, add2(w2, w3)), Bm), M23);
                float4 ov;
                upk(o01, ov.x, ov.y);
                upk(o23, ov.z, ov.w);
                *(float4*)wp = ov;
                Lt=Lm; At=Am; Dt=Dm; Bt=Bm; Rt=Rm;
                Lm=Lb; Am=Ab; Dm=Db; Bm=Bb; Rm=Rb;
                rp += RP; fp += RP; wp += RP;
            }
        }
        __syncthreads();
        float* t = cur; cur = nxt; nxt = t;
    }
    // cur: x after 10 sweeps, valid on [10,76)

    // ---- residual + LFA + MLP epilogue (16x16 logical) ----
    const float w2pih = 6.28318530717958647692f / 513.0f;
    const float cA = k00 + k22, cB = k02 + k20, cC = k01 + k21, cD = k10 + k12;
    const float sA = k22 - k00, sB = k02 - k20, sC = k21 - k01, sD = k12 - k10;
    float* xo = xout + b * N * N;

    // closed form for the linear half of gelu: sum_j 0.5*W2_j*v_j
    float S1 = 0.f, S2 = 0.f, S3 = ssb2;
    #pragma unroll 8
    for (int j = 0; j < HID; ++j) {
        float wo = lo32(sWo[j]);
        S1 = fmaf(wo, lo32(sWa[j]), S1);
        S2 = fmaf(wo, lo32(sWb[j]), S2);
        S3 = fmaf(wo, lo32(sBb[j]), S3);
    }

    const int etx = tid & 15, ety = tid >> 4;   // 16 x 16 logical
    const int ys_e = HALO + ety * 4;
    float s2a[4], c2a[4];
    #pragma unroll
    for (int i = 0; i < 4; ++i)
        __sincosf(w2pih * (float)(gy0v + ys_e + i - 256), &s2a[i], &c2a[i]);

    const ull K1 = pk(0.03567740814f, 0.03567740814f);
    const ull K0 = pk(0.7978845608f,  0.7978845608f);
    const ull Z  = pk(0.f, 0.f);

    #pragma unroll 1
    for (int g = 0; g < 4; ++g) {
        const int cx = HALO + etx + g*16;
        const int gx = gx0v + cx;
        float s1, c1;
        __sincosf(w2pih * (float)(gx - 256), &s1, &c1);

        const float* rp0 = &cur[(ys_e-1)*RP + cx];
        float t0 = rp0[-1],   t1 = rp0[0],  t2 = rp0[1];
        float m0 = rp0[RP-1], m1 = rp0[RP], m2 = rp0[RP+1];
        float rl[4], ll[4], xold[4];
        #pragma unroll
        for (int i = 0; i < 4; ++i) {
            const float* nn = rp0 + (i+2)*RP;
            float n0 = nn[-1], n1 = nn[0], n2 = nn[1];
            float a1 = fs[(ys_e+i)*RP + cx];
            a1 = fmaf(nk00,t0,a1); a1 = fmaf(nk01,t1,a1); a1 = fmaf(nk02,t2,a1);
            float a2 = nk10*m0;    a2 = fmaf(nk11,m1,a2); a2 = fmaf(nk12,m2,a2);
            float a3 = nk20*n0;    a3 = fmaf(nk21,n1,a3); a3 = fmaf(nk22,n2,a3);
            rl[i] = a1 + a2 + a3;
            xold[i] = m1;
            float ssv = s1*s2a[i], cc = c1*c2a[i], sc = s1*c2a[i], cs = c1*s2a[i];
            float cpp = cc - ssv, spp = sc + cs;
            float cpm = cc + ssv, spm = sc - cs;
            float ReS = cA*cpp + cB*cpm + cC*c2a[i] + cD*c1 + k11;
            float ImS = sA*spp + sB*spm + sC*s2a[i] + sD*s1;
            float Re = fmaf(-tau, ReS, 1.f);
            float Im = -tau * ImS;
            float mg2 = fmaf(Re, Re, Im*Im);
            ll[i] = mg2 * mg2 * sqrt_ap(mg2);   // |1-tau*S|^5
            t0=m0; t1=m1; t2=m2;
            m0=n0; m1=n1; m2=n2;
        }
        ull Rr0 = pk(rl[0], rl[1]), Rr1 = pk(rl[2], rl[3]);
        ull LF0 = pk(ll[0], ll[1]), LF1 = pk(ll[2], ll[3]);
        ull acc20 = Z, acc21 = Z;
        #pragma unroll 4
        for (int j = 0; j < HID; ++j) {
            const ull wa = sWa[j], wb = sWb[j], bb = sBb[j], wo = sWo[j];
            {
                ull v  = fma2(wa, LF0, fma2(wb, Rr0, bb));
                ull v2 = mul2(v, v);
                ull q  = fma2(v2, K1, K0);
                ull t  = mul2(v, q);
                float tl, th; upk(t, tl, th);
                ull T  = pk(tanh_ap(tl), tanh_ap(th));
                acc20 = fma2(mul2(v, wo), T, acc20);
            }
            {
                ull v  = fma2(wa, LF1, fma2(wb, Rr1, bb));
                ull v2 = mul2(v, v);
                ull q  = fma2(v2, K1, K0);
                ull t  = mul2(v, q);
                float tl, th; upk(t, tl, th);
                ull T  = pk(tanh_ap(tl), tanh_ap(th));
                acc21 = fma2(mul2(v, wo), T, acc21);
            }
        }
        float e0,e1,e2,e3;
        upk(acc20, e0, e1); upk(acc21, e2, e3);
        float ev[4] = {e0, e1, e2, e3};
        #pragma unroll
        for (int i = 0; i < 4; ++i) {
            float u = fmaf(S1, ll[i], fmaf(S2, rl[i], S3));
            xo[(gy0v + ys_e + i)*N + gx] = xold[i] + ev[i] + u;
        }
    }
}

__global__ void __launch_bounds__(256)
reduce_kernel(const float* __restrict__ f, const float* __restrict__ kA)
{
    __shared__ float xt[(TILE+2)*(TILE+4)];   // 66 x 68 pitch
    __shared__ float redbuf[16];
    const int b   = blockIdx.z;
    const int tid = threadIdx.y*32 + threadIdx.x;
    const float* xb = g_x1 + b*N*N;           // final x lives in g_x1
    const float* fb = f    + b*N*N;
    const int gx0v = blockIdx.x*TILE - 1;
    const int gy0v = blockIdx.y*TILE - 1;

    for (int idx = tid; idx < 66*66; idx += 256) {
        int ly = idx / 66, lx = idx - ly*66;
        int gy = gy0v + ly, gx = gx0v + lx;
        xt[ly*68 + lx] = ((unsigned)gx < N && (unsigned)gy < N) ? xb[gy*N + gx] : 0.f;
    }
    const float* kb = kA + b * 9;
    const float k00 = __ldg(kb+0), k01 = __ldg(kb+1), k02 = __ldg(kb+2);
    const float k10 = __ldg(kb+3), k11 = __ldg(kb+4), k12 = __ldg(kb+5);
    const float k20 = __ldg(kb+6), k21 = __ldg(kb+7), k22 = __ldg(kb+8);
    __syncthreads();

    float sr = 0.f, sf = 0.f;
    for (int ry = threadIdx.y; ry < TILE; ry += 8) {
        for (int rx = threadIdx.x; rx < TILE; rx += 32) {
            int ly = ry + 1, lx = rx + 1;
            const float* c = &xt[ly*68 + lx];
            float ax = k00*c[-69] + k01*c[-68] + k02*c[-67]
                     + k10*c[-1]  + k11*c[0]   + k12*c[1]
                     + k20*c[67]  + k21*c[68]  + k22*c[69];
            float fv = fb[(gy0v+ly)*N + (gx0v+lx)];
            float r = fv - ax;
            sr = fmaf(r, r, sr);
            sf = fmaf(fv, fv, sf);
        }
    }
    #pragma unroll
    for (int o = 16; o; o >>= 1) {
        sr += __shfl_down_sync(0xffffffffu, sr, o);
        sf += __shfl_down_sync(0xffffffffu, sf, o);
    }
    if (threadIdx.x == 0) { redbuf[threadIdx.y] = sr; redbuf[8+threadIdx.y] = sf; }
    __syncthreads();
    if (tid == 0) {
        float a = 0.f, bb = 0.f;
        #pragma unroll
        for (int i = 0; i < 8; ++i) { a += redbuf[i]; bb += redbuf[8+i]; }
        atomicAdd(&g_acc[0], (double)a);
        atomicAdd(&g_acc[1], (double)bb);
    }
}

__global__ void finalize_kernel(float* out) {
    out[0] = (float)sqrt(g_acc[0] / g_acc[1]);
}

extern "C" void kernel_launch(void* const* d_in, const int* in_sizes, int n_in,
                              void* d_out, int out_size)
{
    // metadata order: f, kernelA, u(unused), W1, b1, W2, b2, epoch(=201 -> K=3)
    const float* f  = (const float*)d_in[0];
    const float* kA = (const float*)d_in[1];
    const float* W1 = (const float*)d_in[3];
    const float* b1 = (const float*)d_in[4];
    const float* W2 = (const float*)d_in[5];
    const float* b2 = (const float*)d_in[6];
    float* out = (float*)d_out;

    cudaFuncSetAttribute(iter_kernel, cudaFuncAttributeMaxDynamicSharedMemorySize, SMEM_BYTES);

    dim3 grid(N/TILE, N/TILE, BSZ);   // (8, 8, 16)
    dim3 blk(32, 8);                  // 256 threads
    dim3 blkR(32, 8);

    zero_acc_kernel<<<1, 32>>>();
    // K = 3 outer cycles; x ping-pongs g_x0 <-> g_x1 (starts at zero)
    iter_kernel<<<grid, blk, SMEM_BYTES>>>(0, 1, f, kA, W1, b1, W2, b2); // 0 -> x1
    iter_kernel<<<grid, blk, SMEM_BYTES>>>(1, 0, f, kA, W1, b1, W2, b2); // x1 -> x0
    iter_kernel<<<grid, blk, SMEM_BYTES>>>(0, 0, f, kA, W1, b1, W2, b2); // x0 -> x1
    reduce_kernel<<<grid, blkR>>>(f, kA);
    finalize_kernel<<<1, 1>>>(out);
}